// round 2
// baseline (speedup 1.0000x reference)
#include <cuda_runtime.h>
#include <cstdint>

#define NMAX   100000
#define NGRAPH 512
#define D      128

// ---------------- scratch (device globals; no allocation allowed) ----------------
__device__ __align__(16) float g_s [(size_t)NMAX * D];   // segment sums (zero at scatter start)
__device__ __align__(16) float g_m [(size_t)NMAX * D];   // mean buffer
__device__ __align__(16) float g_h1[(size_t)NMAX * D];
__device__ __align__(16) float g_h2[(size_t)NMAX * D];
__device__ int   g_cnt[NMAX];
__device__ __align__(16) float g_pool[NGRAPH * D];
__device__ int   g_gcnt[NGRAPH];

// ---------------- misc zeroing (cnt / pool / gcnt; g_s kept zero by finalize) ----
__global__ void zero_misc(int N) {
    int i = blockIdx.x * blockDim.x + threadIdx.x;
    if (i < N)          g_cnt[i]  = 0;
    if (i < NGRAPH * D) g_pool[i] = 0.f;
    if (i < NGRAPH)     g_gcnt[i] = 0;
}

// ---------------- in-degree ----------------
__global__ void degree_kernel(const int* __restrict__ ei, int E) {
    int e = blockIdx.x * blockDim.x + threadIdx.x;
    if (e < E) atomicAdd(&g_cnt[ei[E + e]], 1);
}

// ---------------- per-graph node counts ----------------
__global__ void gcnt_kernel(const int* __restrict__ batch, int N) {
    int i = blockIdx.x * blockDim.x + threadIdx.x;
    if (i < N) atomicAdd(&g_gcnt[batch[i]], 1);
}

// ---------------- edge scatter: s[dst] += feat[src] (vectorized red) -------------
__global__ void scatter_kernel(const float* __restrict__ feat_ext, int use_ext,
                               const int* __restrict__ ei, int E) {
    const float* feat = use_ext ? feat_ext : g_h1;
    long long gt = (long long)blockIdx.x * blockDim.x + threadIdx.x;
    int e    = (int)(gt >> 5);
    int lane = threadIdx.x & 31;
    if (e >= E) return;
    int s = ei[e];
    int d = ei[E + e];
    const float4 v = *(const float4*)(feat + (size_t)s * D + lane * 4);
    float* p = g_s + (size_t)d * D + lane * 4;
    asm volatile("red.global.add.v4.f32 [%0], {%1,%2,%3,%4};"
                 :: "l"(p), "f"(v.x), "f"(v.y), "f"(v.z), "f"(v.w) : "memory");
}

// ---------------- finalize: m = s / max(cnt,1); s = 0 ----------------------------
__global__ void finalize_kernel(int N) {
    long long idx = (long long)blockIdx.x * blockDim.x + threadIdx.x;
    if (idx >= (long long)N * 32) return;
    int i = (int)(idx >> 5);
    float invc = 1.f / fmaxf((float)g_cnt[i], 1.f);
    float4* s4 = (float4*)g_s;
    float4* m4 = (float4*)g_m;
    float4 v = s4[idx];
    m4[idx] = make_float4(v.x * invc, v.y * invc, v.z * invc, v.w * invc);
    s4[idx] = make_float4(0.f, 0.f, 0.f, 0.f);
}

// ---------------- fused SAGE linear: out = relu(m @ W0^T + A1 @ W1^T + b) --------
// K=256 fp32 GEMM (first 128 K from g_m/W0, next 128 from A1/W1).
// BM=128, BN=128, BK=16, 256 threads, TM=TN=8.
__global__ void __launch_bounds__(256, 2)
gemm_sage(const float* __restrict__ A1_ext, int use_ext_A,
          const float* __restrict__ W0, const float* __restrict__ W1,
          const float* __restrict__ bias, int which_out, int N) {
    const float* A1  = use_ext_A ? A1_ext : g_h1;
    float*       out = which_out ? g_h2 : g_h1;

    __shared__ __align__(16) float As[16][128];
    __shared__ __align__(16) float Bs[16][128];

    const int block_m = blockIdx.x * 128;
    const int tid = threadIdx.x;
    const int tr  = tid >> 4;   // 0..15 -> rows tr*8..tr*8+7
    const int tc  = tid & 15;   // 0..15 -> cols tc*8..tc*8+7

    float acc[8][8];
    #pragma unroll
    for (int i = 0; i < 8; i++)
        #pragma unroll
        for (int j = 0; j < 8; j++) acc[i][j] = 0.f;

    for (int kc = 0; kc < 256; kc += 16) {
        const float* A = (kc < 128) ? g_m : A1;
        const float* W = (kc < 128) ? W0  : W1;
        const int kcol = kc & 127;

        // A tile: 128 rows x 16 k, transposed into As[k][m]
        #pragma unroll
        for (int it = 0; it < 2; it++) {
            int idx = tid + it * 256;        // 0..511
            int m   = idx >> 2;              // 0..127
            int q   = idx & 3;               // float4 slot
            int row = block_m + m;
            float4 v = make_float4(0.f, 0.f, 0.f, 0.f);
            if (row < N) v = *(const float4*)(A + (size_t)row * D + kcol + q * 4);
            As[q * 4 + 0][m] = v.x; As[q * 4 + 1][m] = v.y;
            As[q * 4 + 2][m] = v.z; As[q * 4 + 3][m] = v.w;
        }
        // B tile: Bs[k][n] = W[n][kcol+k]
        #pragma unroll
        for (int it = 0; it < 2; it++) {
            int idx = tid + it * 256;        // 0..511
            int kq  = idx >> 7;              // 0..3
            int n   = idx & 127;
            float4 v = *(const float4*)(W + (size_t)n * D + kcol + kq * 4);
            Bs[kq * 4 + 0][n] = v.x; Bs[kq * 4 + 1][n] = v.y;
            Bs[kq * 4 + 2][n] = v.z; Bs[kq * 4 + 3][n] = v.w;
        }
        __syncthreads();

        #pragma unroll
        for (int k = 0; k < 16; k++) {
            float4 a0 = *(const float4*)&As[k][tr * 8];
            float4 a1 = *(const float4*)&As[k][tr * 8 + 4];
            float4 b0 = *(const float4*)&Bs[k][tc * 8];
            float4 b1 = *(const float4*)&Bs[k][tc * 8 + 4];
            float a[8] = {a0.x, a0.y, a0.z, a0.w, a1.x, a1.y, a1.z, a1.w};
            float b[8] = {b0.x, b0.y, b0.z, b0.w, b1.x, b1.y, b1.z, b1.w};
            #pragma unroll
            for (int i = 0; i < 8; i++)
                #pragma unroll
                for (int j = 0; j < 8; j++) acc[i][j] += a[i] * b[j];
        }
        __syncthreads();
    }

    float bb[8];
    #pragma unroll
    for (int j = 0; j < 8; j++) bb[j] = bias[tc * 8 + j];

    #pragma unroll
    for (int i = 0; i < 8; i++) {
        int row = block_m + tr * 8 + i;
        if (row < N) {
            float* op = out + (size_t)row * D + tc * 8;
            #pragma unroll
            for (int j = 0; j < 8; j++) op[j] = fmaxf(acc[i][j] + bb[j], 0.f);
        }
    }
}

// ---------------- global mean pool (sum part) ----------------
__global__ void pool_kernel(const int* __restrict__ batch, int N) {
    long long gt = (long long)blockIdx.x * blockDim.x + threadIdx.x;
    int node = (int)(gt >> 5);
    int lane = threadIdx.x & 31;
    if (node >= N) return;
    int b = batch[node];
    const float4 v = *(const float4*)(g_h2 + (size_t)node * D + lane * 4);
    float* p = g_pool + (size_t)b * D + lane * 4;
    asm volatile("red.global.add.v4.f32 [%0], {%1,%2,%3,%4};"
                 :: "l"(p), "f"(v.x), "f"(v.y), "f"(v.z), "f"(v.w) : "memory");
}

// ---------------- head: logits + log_softmax (one warp per graph) ----------------
__global__ void final_kernel(const float* __restrict__ Wf, const float* __restrict__ bf,
                             float* __restrict__ out) {
    int b = blockIdx.x;
    int lane = threadIdx.x;  // 32
    float invg = 1.f / fmaxf((float)g_gcnt[b], 1.f);
    float gm[4];
    #pragma unroll
    for (int q = 0; q < 4; q++) gm[q] = g_pool[b * D + q * 32 + lane] * invg;

    float logit[10];
    #pragma unroll
    for (int o = 0; o < 10; o++) {
        float p = 0.f;
        #pragma unroll
        for (int q = 0; q < 4; q++) p += gm[q] * Wf[o * D + q * 32 + lane];
        #pragma unroll
        for (int off = 16; off; off >>= 1) p += __shfl_xor_sync(0xffffffffu, p, off);
        logit[o] = p + bf[o];
    }
    float mx = logit[0];
    #pragma unroll
    for (int o = 1; o < 10; o++) mx = fmaxf(mx, logit[o]);
    float ssum = 0.f;
    #pragma unroll
    for (int o = 0; o < 10; o++) ssum += expf(logit[o] - mx);
    float lse = logf(ssum);
    if (lane < 10) out[b * 10 + lane] = logit[lane] - mx - lse;
}

// ---------------- launch ----------------
extern "C" void kernel_launch(void* const* d_in, const int* in_sizes, int n_in,
                              void* d_out, int out_size) {
    const float* x     = (const float*)d_in[0];
    const int*   ei    = (const int*)d_in[1];
    const int*   batch = (const int*)d_in[2];
    const float* W1l = (const float*)d_in[3];
    const float* b1  = (const float*)d_in[4];
    const float* W1r = (const float*)d_in[5];
    const float* W2l = (const float*)d_in[6];
    const float* b2  = (const float*)d_in[7];
    const float* W2r = (const float*)d_in[8];
    const float* Wf  = (const float*)d_in[9];
    const float* bf  = (const float*)d_in[10];
    float* out = (float*)d_out;

    int N = in_sizes[0] / D;     // 100000
    int E = in_sizes[1] / 2;     // 1600000
    int G = out_size / 10;       // 512

    int tpb = 256;
    int blkN   = (N + tpb - 1) / tpb;
    int blkE   = (E + tpb - 1) / tpb;
    long long scatT = (long long)E * 32;
    int blkScat = (int)((scatT + tpb - 1) / tpb);
    long long finT = (long long)N * 32;
    int blkFin = (int)((finT + tpb - 1) / tpb);
    int blkGemm = (N + 127) / 128;

    zero_misc<<<blkN, tpb>>>(N);
    degree_kernel<<<blkE, tpb>>>(ei, E);
    gcnt_kernel<<<blkN, tpb>>>(batch, N);

    // layer 1
    scatter_kernel<<<blkScat, tpb>>>(x, 1, ei, E);
    finalize_kernel<<<blkFin, tpb>>>(N);
    gemm_sage<<<blkGemm, tpb>>>(x, 1, W1l, W1r, b1, /*which_out=h1*/0, N);

    // layer 2
    scatter_kernel<<<blkScat, tpb>>>(nullptr, 0, ei, E);   // feat = g_h1
    finalize_kernel<<<blkFin, tpb>>>(N);
    gemm_sage<<<blkGemm, tpb>>>(nullptr, 0, W2l, W2r, b2, /*which_out=h2*/1, N);

    // pooling + head
    pool_kernel<<<blkFin, tpb>>>(batch, N);
    final_kernel<<<G, 32>>>(Wf, bf, out);
}

// round 3
// speedup vs baseline: 1.4935x; 1.4935x over previous
#include <cuda_runtime.h>
#include <cstdint>

#define NMAX   100000
#define EMAX   1600000
#define NGRAPH 512
#define D      128
#define SCANB  512   // elements per scan block

// ---------------- scratch (device globals; no allocation allowed) ----------------
__device__ __align__(16) float g_m [(size_t)NMAX * D];   // mean buffer
__device__ __align__(16) float g_h1[(size_t)NMAX * D];
__device__ __align__(16) float g_h2[(size_t)NMAX * D];
__device__ int   g_cnt[NMAX];          // in-degree
__device__ int   g_scan[NMAX];         // inclusive scan within block
__device__ int   g_bsum[(NMAX + SCANB - 1) / SCANB];
__device__ int   g_bsumx[(NMAX + SCANB - 1) / SCANB];
__device__ int   g_rowstart[NMAX + 1];
__device__ int   g_cursor[NMAX];
__device__ int   g_csrc[EMAX];         // CSR: src ids grouped by dst
__device__ __align__(16) float g_pool[NGRAPH * D];
__device__ int   g_gcnt[NGRAPH];

// ---------------- zero cnt / pool / gcnt ----------------
__global__ void zero_misc(int N) {
    int i = blockIdx.x * blockDim.x + threadIdx.x;
    if (i < N)          g_cnt[i]  = 0;
    if (i < NGRAPH * D) g_pool[i] = 0.f;
    if (i < NGRAPH)     g_gcnt[i] = 0;
}

// ---------------- in-degree + per-graph node counts ----------------
__global__ void degree_kernel(const int* __restrict__ ei, int E) {
    int e = blockIdx.x * blockDim.x + threadIdx.x;
    if (e < E) atomicAdd(&g_cnt[ei[E + e]], 1);
}
__global__ void gcnt_kernel(const int* __restrict__ batch, int N) {
    int i = blockIdx.x * blockDim.x + threadIdx.x;
    if (i < N) atomicAdd(&g_gcnt[batch[i]], 1);
}

// ---------------- scan stage 1: per-block inclusive scan of g_cnt ----------------
__global__ void scan1_kernel(int N) {
    __shared__ int sm[SCANB];
    int i = blockIdx.x * SCANB + threadIdx.x;
    int v = (i < N) ? g_cnt[i] : 0;
    sm[threadIdx.x] = v;
    __syncthreads();
    #pragma unroll
    for (int off = 1; off < SCANB; off <<= 1) {
        int t = (threadIdx.x >= off) ? sm[threadIdx.x - off] : 0;
        __syncthreads();
        sm[threadIdx.x] += t;
        __syncthreads();
    }
    if (i < N) g_scan[i] = sm[threadIdx.x];
    if (threadIdx.x == SCANB - 1) g_bsum[blockIdx.x] = sm[SCANB - 1];
}

// ---------------- scan stage 2: exclusive scan of block sums (one block) ---------
__global__ void scan2_kernel(int NB) {
    __shared__ int sm[SCANB];
    int v = (threadIdx.x < NB) ? g_bsum[threadIdx.x] : 0;
    sm[threadIdx.x] = v;
    __syncthreads();
    #pragma unroll
    for (int off = 1; off < SCANB; off <<= 1) {
        int t = (threadIdx.x >= off) ? sm[threadIdx.x - off] : 0;
        __syncthreads();
        sm[threadIdx.x] += t;
        __syncthreads();
    }
    if (threadIdx.x < NB) g_bsumx[threadIdx.x] = sm[threadIdx.x] - v;  // exclusive
}

// ---------------- scan stage 3: rowstart / cursor ----------------
__global__ void scan3_kernel(int N, int E) {
    int i = blockIdx.x * blockDim.x + threadIdx.x;
    if (i < N) {
        int rs = g_scan[i] - g_cnt[i] + g_bsumx[i / SCANB];
        g_rowstart[i] = rs;
        g_cursor[i]   = rs;
    }
    if (i == 0) g_rowstart[N] = E;
}

// ---------------- edge placement into CSR ----------------
__global__ void place_kernel(const int* __restrict__ ei, int E) {
    int e = blockIdx.x * blockDim.x + threadIdx.x;
    if (e >= E) return;
    int s = ei[e];
    int d = ei[E + e];
    int pos = atomicAdd(&g_cursor[d], 1);
    g_csrc[pos] = s;
}

// ---------------- gather-mean: m[i] = mean_{j in N(i)} feat[j] -------------------
// one warp per node; lane q holds float4 covering cols q*4..q*4+3
__global__ void __launch_bounds__(256)
gather_mean(const float* __restrict__ feat_ext, int use_ext, int N) {
    const float* feat = use_ext ? feat_ext : g_h1;
    int warp = (blockIdx.x * blockDim.x + threadIdx.x) >> 5;
    if (warp >= N) return;
    int lane = threadIdx.x & 31;
    int beg = g_rowstart[warp];
    int end = g_rowstart[warp + 1];

    float4 acc = make_float4(0.f, 0.f, 0.f, 0.f);
    int j = beg;
    for (; j + 4 <= end; j += 4) {
        int s0 = g_csrc[j + 0];
        int s1 = g_csrc[j + 1];
        int s2 = g_csrc[j + 2];
        int s3 = g_csrc[j + 3];
        float4 v0 = *(const float4*)(feat + (size_t)s0 * D + lane * 4);
        float4 v1 = *(const float4*)(feat + (size_t)s1 * D + lane * 4);
        float4 v2 = *(const float4*)(feat + (size_t)s2 * D + lane * 4);
        float4 v3 = *(const float4*)(feat + (size_t)s3 * D + lane * 4);
        acc.x += v0.x + v1.x + v2.x + v3.x;
        acc.y += v0.y + v1.y + v2.y + v3.y;
        acc.z += v0.z + v1.z + v2.z + v3.z;
        acc.w += v0.w + v1.w + v2.w + v3.w;
    }
    for (; j < end; j++) {
        int s = g_csrc[j];
        float4 v = *(const float4*)(feat + (size_t)s * D + lane * 4);
        acc.x += v.x; acc.y += v.y; acc.z += v.z; acc.w += v.w;
    }
    float invc = 1.f / fmaxf((float)(end - beg), 1.f);
    float4* m4 = (float4*)(g_m + (size_t)warp * D);
    m4[lane] = make_float4(acc.x * invc, acc.y * invc, acc.z * invc, acc.w * invc);
}

// ---------------- fused SAGE linear: out = relu(m @ W0^T + A1 @ W1^T + b) --------
// K=256 fp32 GEMM. BM=128, BN=128, BK=16, 256 threads, TM=TN=8.
__global__ void __launch_bounds__(256, 2)
gemm_sage(const float* __restrict__ A1_ext, int use_ext_A,
          const float* __restrict__ W0, const float* __restrict__ W1,
          const float* __restrict__ bias, int which_out, int N) {
    const float* A1  = use_ext_A ? A1_ext : g_h1;
    float*       out = which_out ? g_h2 : g_h1;

    __shared__ __align__(16) float As[16][128];
    __shared__ __align__(16) float Bs[16][128];

    const int block_m = blockIdx.x * 128;
    const int tid = threadIdx.x;
    const int tr  = tid >> 4;
    const int tc  = tid & 15;

    float acc[8][8];
    #pragma unroll
    for (int i = 0; i < 8; i++)
        #pragma unroll
        for (int j = 0; j < 8; j++) acc[i][j] = 0.f;

    for (int kc = 0; kc < 256; kc += 16) {
        const float* A = (kc < 128) ? g_m : A1;
        const float* W = (kc < 128) ? W0  : W1;
        const int kcol = kc & 127;

        #pragma unroll
        for (int it = 0; it < 2; it++) {
            int idx = tid + it * 256;
            int m   = idx >> 2;
            int q   = idx & 3;
            int row = block_m + m;
            float4 v = make_float4(0.f, 0.f, 0.f, 0.f);
            if (row < N) v = *(const float4*)(A + (size_t)row * D + kcol + q * 4);
            As[q * 4 + 0][m] = v.x; As[q * 4 + 1][m] = v.y;
            As[q * 4 + 2][m] = v.z; As[q * 4 + 3][m] = v.w;
        }
        #pragma unroll
        for (int it = 0; it < 2; it++) {
            int idx = tid + it * 256;
            int kq  = idx >> 7;
            int n   = idx & 127;
            float4 v = *(const float4*)(W + (size_t)n * D + kcol + kq * 4);
            Bs[kq * 4 + 0][n] = v.x; Bs[kq * 4 + 1][n] = v.y;
            Bs[kq * 4 + 2][n] = v.z; Bs[kq * 4 + 3][n] = v.w;
        }
        __syncthreads();

        #pragma unroll
        for (int k = 0; k < 16; k++) {
            float4 a0 = *(const float4*)&As[k][tr * 8];
            float4 a1 = *(const float4*)&As[k][tr * 8 + 4];
            float4 b0 = *(const float4*)&Bs[k][tc * 8];
            float4 b1 = *(const float4*)&Bs[k][tc * 8 + 4];
            float a[8] = {a0.x, a0.y, a0.z, a0.w, a1.x, a1.y, a1.z, a1.w};
            float b[8] = {b0.x, b0.y, b0.z, b0.w, b1.x, b1.y, b1.z, b1.w};
            #pragma unroll
            for (int i = 0; i < 8; i++)
                #pragma unroll
                for (int j = 0; j < 8; j++) acc[i][j] += a[i] * b[j];
        }
        __syncthreads();
    }

    float bb[8];
    #pragma unroll
    for (int j = 0; j < 8; j++) bb[j] = bias[tc * 8 + j];

    #pragma unroll
    for (int i = 0; i < 8; i++) {
        int row = block_m + tr * 8 + i;
        if (row < N) {
            float* op = out + (size_t)row * D + tc * 8;
            #pragma unroll
            for (int j = 0; j < 8; j++) op[j] = fmaxf(acc[i][j] + bb[j], 0.f);
        }
    }
}

// ---------------- global mean pool (sum part) ----------------
__global__ void pool_kernel(const int* __restrict__ batch, int N) {
    long long gt = (long long)blockIdx.x * blockDim.x + threadIdx.x;
    int node = (int)(gt >> 5);
    int lane = threadIdx.x & 31;
    if (node >= N) return;
    int b = batch[node];
    const float4 v = *(const float4*)(g_h2 + (size_t)node * D + lane * 4);
    float* p = g_pool + (size_t)b * D + lane * 4;
    asm volatile("red.global.add.v4.f32 [%0], {%1,%2,%3,%4};"
                 :: "l"(p), "f"(v.x), "f"(v.y), "f"(v.z), "f"(v.w) : "memory");
}

// ---------------- head: logits + log_softmax (one warp per graph) ----------------
__global__ void final_kernel(const float* __restrict__ Wf, const float* __restrict__ bf,
                             float* __restrict__ out) {
    int b = blockIdx.x;
    int lane = threadIdx.x;
    float invg = 1.f / fmaxf((float)g_gcnt[b], 1.f);
    float gm[4];
    #pragma unroll
    for (int q = 0; q < 4; q++) gm[q] = g_pool[b * D + q * 32 + lane] * invg;

    float logit[10];
    #pragma unroll
    for (int o = 0; o < 10; o++) {
        float p = 0.f;
        #pragma unroll
        for (int q = 0; q < 4; q++) p += gm[q] * Wf[o * D + q * 32 + lane];
        #pragma unroll
        for (int off = 16; off; off >>= 1) p += __shfl_xor_sync(0xffffffffu, p, off);
        logit[o] = p + bf[o];
    }
    float mx = logit[0];
    #pragma unroll
    for (int o = 1; o < 10; o++) mx = fmaxf(mx, logit[o]);
    float ssum = 0.f;
    #pragma unroll
    for (int o = 0; o < 10; o++) ssum += expf(logit[o] - mx);
    float lse = logf(ssum);
    if (lane < 10) out[b * 10 + lane] = logit[lane] - mx - lse;
}

// ---------------- launch ----------------
extern "C" void kernel_launch(void* const* d_in, const int* in_sizes, int n_in,
                              void* d_out, int out_size) {
    const float* x     = (const float*)d_in[0];
    const int*   ei    = (const int*)d_in[1];
    const int*   batch = (const int*)d_in[2];
    const float* W1l = (const float*)d_in[3];
    const float* b1  = (const float*)d_in[4];
    const float* W1r = (const float*)d_in[5];
    const float* W2l = (const float*)d_in[6];
    const float* b2  = (const float*)d_in[7];
    const float* W2r = (const float*)d_in[8];
    const float* Wf  = (const float*)d_in[9];
    const float* bf  = (const float*)d_in[10];
    float* out = (float*)d_out;

    int N = in_sizes[0] / D;     // 100000
    int E = in_sizes[1] / 2;     // 1600000
    int G = out_size / 10;       // 512

    int tpb = 256;
    int blkN  = (N + tpb - 1) / tpb;
    int blkE  = (E + tpb - 1) / tpb;
    int NB    = (N + SCANB - 1) / SCANB;
    long long warpT = (long long)N * 32;
    int blkWarp = (int)((warpT + tpb - 1) / tpb);
    int blkGemm = (N + 127) / 128;

    // CSR build (once, reused by both layers)
    zero_misc<<<blkN, tpb>>>(N);
    degree_kernel<<<blkE, tpb>>>(ei, E);
    gcnt_kernel<<<blkN, tpb>>>(batch, N);
    scan1_kernel<<<NB, SCANB>>>(N);
    scan2_kernel<<<1, SCANB>>>(NB);
    scan3_kernel<<<blkN, tpb>>>(N, E);
    place_kernel<<<blkE, tpb>>>(ei, E);

    // layer 1
    gather_mean<<<blkWarp, tpb>>>(x, 1, N);
    gemm_sage<<<blkGemm, tpb>>>(x, 1, W1l, W1r, b1, /*out=h1*/0, N);

    // layer 2
    gather_mean<<<blkWarp, tpb>>>(nullptr, 0, N);
    gemm_sage<<<blkGemm, tpb>>>(nullptr, 0, W2l, W2r, b2, /*out=h2*/1, N);

    // pooling + head
    pool_kernel<<<blkWarp, tpb>>>(batch, N);
    final_kernel<<<G, 32>>>(Wf, bf, out);
}

// round 4
// speedup vs baseline: 2.5997x; 1.7407x over previous
#include <cuda_runtime.h>
#include <cstdint>

#define NMAX   100000
#define EMAX   1600000
#define NGRAPH 512
#define D      128
#define SCANB  512

// ---------------- scratch (device globals) ----------------
__device__ __align__(16) float g_m [(size_t)NMAX * D];
__device__ __align__(16) float g_h1[(size_t)NMAX * D];
__device__ __align__(16) float g_h2[(size_t)NMAX * D];
__device__ int   g_cnt[NMAX];
__device__ int   g_scan[NMAX];
__device__ int   g_bsum[(NMAX + SCANB - 1) / SCANB];
__device__ int   g_bsumx[(NMAX + SCANB - 1) / SCANB];
__device__ int   g_rowstart[NMAX + 1];
__device__ int   g_cursor[NMAX];
__device__ int   g_csrc[EMAX];
__device__ __align__(16) float g_pool[NGRAPH * D];
__device__ int   g_gcnt[NGRAPH];

__device__ __forceinline__ uint32_t f2tf32(float f) {
    uint32_t u;
    asm("cvt.rna.tf32.f32 %0, %1;" : "=r"(u) : "f"(f));
    return u;
}

// ---------------- zero cnt / pool / gcnt ----------------
__global__ void zero_misc(int N) {
    int i = blockIdx.x * blockDim.x + threadIdx.x;
    if (i < N)          g_cnt[i]  = 0;
    if (i < NGRAPH * D) g_pool[i] = 0.f;
    if (i < NGRAPH)     g_gcnt[i] = 0;
}

// ---------------- degrees ----------------
__global__ void degree_kernel(const int* __restrict__ ei, int E) {
    int e = blockIdx.x * blockDim.x + threadIdx.x;
    if (e < E) atomicAdd(&g_cnt[ei[E + e]], 1);
}
__global__ void gcnt_kernel(const int* __restrict__ batch, int N) {
    int i = blockIdx.x * blockDim.x + threadIdx.x;
    if (i < N) atomicAdd(&g_gcnt[batch[i]], 1);
}

// ---------------- scan stages ----------------
__global__ void scan1_kernel(int N) {
    __shared__ int sm[SCANB];
    int i = blockIdx.x * SCANB + threadIdx.x;
    int v = (i < N) ? g_cnt[i] : 0;
    sm[threadIdx.x] = v;
    __syncthreads();
    #pragma unroll
    for (int off = 1; off < SCANB; off <<= 1) {
        int t = (threadIdx.x >= off) ? sm[threadIdx.x - off] : 0;
        __syncthreads();
        sm[threadIdx.x] += t;
        __syncthreads();
    }
    if (i < N) g_scan[i] = sm[threadIdx.x];
    if (threadIdx.x == SCANB - 1) g_bsum[blockIdx.x] = sm[SCANB - 1];
}
__global__ void scan2_kernel(int NB) {
    __shared__ int sm[SCANB];
    int v = (threadIdx.x < NB) ? g_bsum[threadIdx.x] : 0;
    sm[threadIdx.x] = v;
    __syncthreads();
    #pragma unroll
    for (int off = 1; off < SCANB; off <<= 1) {
        int t = (threadIdx.x >= off) ? sm[threadIdx.x - off] : 0;
        __syncthreads();
        sm[threadIdx.x] += t;
        __syncthreads();
    }
    if (threadIdx.x < NB) g_bsumx[threadIdx.x] = sm[threadIdx.x] - v;
}
__global__ void scan3_kernel(int N, int E) {
    int i = blockIdx.x * blockDim.x + threadIdx.x;
    if (i < N) {
        int rs = g_scan[i] - g_cnt[i] + g_bsumx[i / SCANB];
        g_rowstart[i] = rs;
        g_cursor[i]   = rs;
    }
    if (i == 0) g_rowstart[N] = E;
}
__global__ void place_kernel(const int* __restrict__ ei, int E) {
    int e = blockIdx.x * blockDim.x + threadIdx.x;
    if (e >= E) return;
    int pos = atomicAdd(&g_cursor[ei[E + e]], 1);
    g_csrc[pos] = ei[e];
}

// ---------------- gather-mean (one warp per node, unroll 8) ----------------
__global__ void __launch_bounds__(256)
gather_mean(const float* __restrict__ feat_ext, int use_ext, int N) {
    const float* feat = use_ext ? feat_ext : g_h1;
    int warp = (blockIdx.x * blockDim.x + threadIdx.x) >> 5;
    if (warp >= N) return;
    int lane = threadIdx.x & 31;
    int beg = g_rowstart[warp];
    int end = g_rowstart[warp + 1];

    float4 acc = make_float4(0.f, 0.f, 0.f, 0.f);
    int j = beg;
    for (; j + 8 <= end; j += 8) {
        int s[8];
        #pragma unroll
        for (int u = 0; u < 8; u++) s[u] = g_csrc[j + u];
        float4 v[8];
        #pragma unroll
        for (int u = 0; u < 8; u++)
            v[u] = *(const float4*)(feat + (size_t)s[u] * D + lane * 4);
        #pragma unroll
        for (int u = 0; u < 8; u++) {
            acc.x += v[u].x; acc.y += v[u].y; acc.z += v[u].z; acc.w += v[u].w;
        }
    }
    for (; j < end; j++) {
        int s = g_csrc[j];
        float4 v = *(const float4*)(feat + (size_t)s * D + lane * 4);
        acc.x += v.x; acc.y += v.y; acc.z += v.z; acc.w += v.w;
    }
    float invc = 1.f / fmaxf((float)(end - beg), 1.f);
    float4* m4 = (float4*)(g_m + (size_t)warp * D);
    m4[lane] = make_float4(acc.x * invc, acc.y * invc, acc.z * invc, acc.w * invc);
}

// ---------------- tf32 tensor-core fused SAGE linear ----------------
// out = relu(g_m @ W0^T + A1 @ W1^T + b). K=256 (128 from each pair).
// BM=128, BN=128, BK=16. 256 thr = 8 warps (4 along M x 2 along N), warp tile 32x64.
#define PADK 20   // 16 k + 4 pad (80B row stride, 16B aligned, conflict-free frags)
__global__ void __launch_bounds__(256, 2)
gemm_sage_tc(const float* __restrict__ A1_ext, int use_ext_A,
             const float* __restrict__ W0, const float* __restrict__ W1,
             const float* __restrict__ bias, int which_out, int N) {
    const float* A1  = use_ext_A ? A1_ext : g_h1;
    float*       out = which_out ? g_h2 : g_h1;

    __shared__ __align__(16) uint32_t As[128][PADK];  // [m][k] tf32 bits
    __shared__ __align__(16) uint32_t Bs[128][PADK];  // [n][k] tf32 bits

    const int tid  = threadIdx.x;
    const int warp = tid >> 5;
    const int lane = tid & 31;
    const int gq   = lane >> 2;   // group id 0..7
    const int tq   = lane & 3;    // thread in group
    const int wm   = (warp >> 1) * 32;  // warp m offset (0,32,64,96)
    const int wn   = (warp & 1) * 64;   // warp n offset (0,64)
    const int block_m = blockIdx.x * 128;

    float acc[2][8][4];
    #pragma unroll
    for (int mt = 0; mt < 2; mt++)
        #pragma unroll
        for (int nt = 0; nt < 8; nt++)
            #pragma unroll
            for (int r = 0; r < 4; r++) acc[mt][nt][r] = 0.f;

    for (int kc = 0; kc < 256; kc += 16) {
        const float* A = (kc < 128) ? g_m : A1;
        const float* W = (kc < 128) ? W0  : W1;
        const int kcol = kc & 127;

        // A tile: 128 rows x 16 k  (512 float4 loads, 2/thread)
        #pragma unroll
        for (int it = 0; it < 2; it++) {
            int idx = tid + it * 256;
            int row = idx >> 2;
            int q   = idx & 3;
            int grow = block_m + row;
            float4 v = make_float4(0.f, 0.f, 0.f, 0.f);
            if (grow < N) v = *(const float4*)(A + (size_t)grow * D + kcol + q * 4);
            uint4 u = make_uint4(f2tf32(v.x), f2tf32(v.y), f2tf32(v.z), f2tf32(v.w));
            *(uint4*)&As[row][q * 4] = u;
        }
        // B tile: 128 n rows x 16 k
        #pragma unroll
        for (int it = 0; it < 2; it++) {
            int idx = tid + it * 256;
            int row = idx >> 2;
            int q   = idx & 3;
            float4 v = *(const float4*)(W + (size_t)row * D + kcol + q * 4);
            uint4 u = make_uint4(f2tf32(v.x), f2tf32(v.y), f2tf32(v.z), f2tf32(v.w));
            *(uint4*)&Bs[row][q * 4] = u;
        }
        __syncthreads();

        #pragma unroll
        for (int ks = 0; ks < 2; ks++) {
            const int k0 = ks * 8;
            uint32_t a[2][4];
            #pragma unroll
            for (int mt = 0; mt < 2; mt++) {
                int r0 = wm + mt * 16 + gq;
                a[mt][0] = As[r0    ][k0 + tq];
                a[mt][1] = As[r0 + 8][k0 + tq];
                a[mt][2] = As[r0    ][k0 + tq + 4];
                a[mt][3] = As[r0 + 8][k0 + tq + 4];
            }
            uint32_t b[8][2];
            #pragma unroll
            for (int nt = 0; nt < 8; nt++) {
                int nr = wn + nt * 8 + gq;
                b[nt][0] = Bs[nr][k0 + tq];
                b[nt][1] = Bs[nr][k0 + tq + 4];
            }
            #pragma unroll
            for (int mt = 0; mt < 2; mt++)
                #pragma unroll
                for (int nt = 0; nt < 8; nt++) {
                    asm volatile(
                        "mma.sync.aligned.m16n8k8.row.col.f32.tf32.tf32.f32 "
                        "{%0,%1,%2,%3},{%4,%5,%6,%7},{%8,%9},{%0,%1,%2,%3};"
                        : "+f"(acc[mt][nt][0]), "+f"(acc[mt][nt][1]),
                          "+f"(acc[mt][nt][2]), "+f"(acc[mt][nt][3])
                        : "r"(a[mt][0]), "r"(a[mt][1]), "r"(a[mt][2]), "r"(a[mt][3]),
                          "r"(b[nt][0]), "r"(b[nt][1]));
                }
        }
        __syncthreads();
    }

    // epilogue: bias + relu, write float2 pairs
    #pragma unroll
    for (int nt = 0; nt < 8; nt++) {
        int col = wn + nt * 8 + 2 * tq;
        float b0 = bias[col], b1 = bias[col + 1];
        #pragma unroll
        for (int mt = 0; mt < 2; mt++) {
            int r0 = block_m + wm + mt * 16 + gq;
            int r1 = r0 + 8;
            if (r0 < N) {
                float2 v = make_float2(fmaxf(acc[mt][nt][0] + b0, 0.f),
                                       fmaxf(acc[mt][nt][1] + b1, 0.f));
                *(float2*)(out + (size_t)r0 * D + col) = v;
            }
            if (r1 < N) {
                float2 v = make_float2(fmaxf(acc[mt][nt][2] + b0, 0.f),
                                       fmaxf(acc[mt][nt][3] + b1, 0.f));
                *(float2*)(out + (size_t)r1 * D + col) = v;
            }
        }
    }
}

// ---------------- global mean pool (sum part) ----------------
__global__ void pool_kernel(const int* __restrict__ batch, int N) {
    long long gt = (long long)blockIdx.x * blockDim.x + threadIdx.x;
    int node = (int)(gt >> 5);
    int lane = threadIdx.x & 31;
    if (node >= N) return;
    int b = batch[node];
    const float4 v = *(const float4*)(g_h2 + (size_t)node * D + lane * 4);
    float* p = g_pool + (size_t)b * D + lane * 4;
    asm volatile("red.global.add.v4.f32 [%0], {%1,%2,%3,%4};"
                 :: "l"(p), "f"(v.x), "f"(v.y), "f"(v.z), "f"(v.w) : "memory");
}

// ---------------- head ----------------
__global__ void final_kernel(const float* __restrict__ Wf, const float* __restrict__ bf,
                             float* __restrict__ out) {
    int b = blockIdx.x;
    int lane = threadIdx.x;
    float invg = 1.f / fmaxf((float)g_gcnt[b], 1.f);
    float gm[4];
    #pragma unroll
    for (int q = 0; q < 4; q++) gm[q] = g_pool[b * D + q * 32 + lane] * invg;

    float logit[10];
    #pragma unroll
    for (int o = 0; o < 10; o++) {
        float p = 0.f;
        #pragma unroll
        for (int q = 0; q < 4; q++) p += gm[q] * Wf[o * D + q * 32 + lane];
        #pragma unroll
        for (int off = 16; off; off >>= 1) p += __shfl_xor_sync(0xffffffffu, p, off);
        logit[o] = p + bf[o];
    }
    float mx = logit[0];
    #pragma unroll
    for (int o = 1; o < 10; o++) mx = fmaxf(mx, logit[o]);
    float ssum = 0.f;
    #pragma unroll
    for (int o = 0; o < 10; o++) ssum += expf(logit[o] - mx);
    float lse = logf(ssum);
    if (lane < 10) out[b * 10 + lane] = logit[lane] - mx - lse;
}

// ---------------- launch ----------------
extern "C" void kernel_launch(void* const* d_in, const int* in_sizes, int n_in,
                              void* d_out, int out_size) {
    const float* x     = (const float*)d_in[0];
    const int*   ei    = (const int*)d_in[1];
    const int*   batch = (const int*)d_in[2];
    const float* W1l = (const float*)d_in[3];
    const float* b1  = (const float*)d_in[4];
    const float* W1r = (const float*)d_in[5];
    const float* W2l = (const float*)d_in[6];
    const float* b2  = (const float*)d_in[7];
    const float* W2r = (const float*)d_in[8];
    const float* Wf  = (const float*)d_in[9];
    const float* bf  = (const float*)d_in[10];
    float* out = (float*)d_out;

    int N = in_sizes[0] / D;
    int E = in_sizes[1] / 2;
    int G = out_size / 10;

    int tpb = 256;
    int blkN  = (N + tpb - 1) / tpb;
    int blkE  = (E + tpb - 1) / tpb;
    int NB    = (N + SCANB - 1) / SCANB;
    long long warpT = (long long)N * 32;
    int blkWarp = (int)((warpT + tpb - 1) / tpb);
    int blkGemm = (N + 127) / 128;

    // CSR build (once)
    zero_misc<<<blkN, tpb>>>(N);
    degree_kernel<<<blkE, tpb>>>(ei, E);
    gcnt_kernel<<<blkN, tpb>>>(batch, N);
    scan1_kernel<<<NB, SCANB>>>(N);
    scan2_kernel<<<1, SCANB>>>(NB);
    scan3_kernel<<<blkN, tpb>>>(N, E);
    place_kernel<<<blkE, tpb>>>(ei, E);

    // layer 1
    gather_mean<<<blkWarp, tpb>>>(x, 1, N);
    gemm_sage_tc<<<blkGemm, tpb>>>(x, 1, W1l, W1r, b1, 0, N);

    // layer 2
    gather_mean<<<blkWarp, tpb>>>(nullptr, 0, N);
    gemm_sage_tc<<<blkGemm, tpb>>>(nullptr, 0, W2l, W2r, b2, 1, N);

    // pooling + head
    pool_kernel<<<blkWarp, tpb>>>(batch, N);
    final_kernel<<<G, 32>>>(Wf, bf, out);
}